// round 2
// baseline (speedup 1.0000x reference)
#include <cuda_runtime.h>

// CorrelationHead fused kernel.
// out[b,o] = bias[o] + sum over the 625 in-bounds (i,j,u,v) pairs of
//            W[o, p*1029 + q*49 + i*7 + j] * dot_c( P1[b,c,i,j], P2[b,c,u,v] )
// where u = i + 2(p-10) in [0,6], v = j + 2(q-10) in [0,6].
// Exploits that only 625/21609 correlation entries are nonzero.

static constexpr int CC        = 128;            // channels
static constexpr int HW        = 49;             // 7x7
static constexpr int FEAT      = 21609;          // 21*21*7*7
static constexpr int S2_STRIDE = 129;            // float4 words per (par,u) row (pad for banks)
static constexpr int S1_FLOATS = CC * HW;        // 6272
static constexpr int S2_WORDS  = 14 * S2_STRIDE; // 2 parities * 7 u * 129 = 1806 float4
static constexpr int SMEM_FLOATS = S1_FLOATS + S2_WORDS * 4 + 32; // + warp-reduce scratch
static constexpr int SMEM_BYTES  = SMEM_FLOATS * 4;               // 54240 B

__global__ __launch_bounds__(256, 4)
void corr_head_kernel(const float* __restrict__ p1,
                      const float* __restrict__ p2,
                      const float* __restrict__ W,
                      const float* __restrict__ bias,
                      float* __restrict__ out)
{
    extern __shared__ float sm[];
    float* s1   = sm;                              // P1: [c][ij], 6272 floats
    float* s2f  = sm + S1_FLOATS;                  // P2 repacked: [(par*7+u)*129 + c] float4 over vi
    float* wred = sm + S1_FLOATS + S2_WORDS * 4;   // 8 warps * 4 outputs

    const int b   = blockIdx.x;
    const int tid = threadIdx.x;
    const float* p1b = p1 + (size_t)b * S1_FLOATS;
    const float* p2b = p2 + (size_t)b * S1_FLOATS;

    // --- Stage P1 into smem (coalesced float4 copy, same layout) ---
    {
        const float4* p1v = reinterpret_cast<const float4*>(p1b);
        float4* s1v = reinterpret_cast<float4*>(s1);
        #pragma unroll 1
        for (int k = tid; k < S1_FLOATS / 4; k += 256) s1v[k] = p1v[k];
    }

    // --- Stage P2 into smem, repacked by v-parity so valid-v taps are a float4 ---
    // value P2[c][u][v] -> word ((v&1)*7 + u)*129 + c, element (v>>1).
    // For odd parity, element 3 of a word is never written (garbage) and never used.
    #pragma unroll 1
    for (int k = tid; k < S1_FLOATS; k += 256) {
        float val = __ldg(p2b + k);
        int c  = k / 49;
        int uv = k - c * 49;
        int u  = uv / 7;
        int v  = uv - u * 7;
        int word = ((v & 1) * 7 + u) * S2_STRIDE + c;
        s2f[word * 4 + (v >> 1)] = val;
    }
    __syncthreads();

    // --- Compute: thread slot = (ij, ui). 49*4 = 196 active slots. ---
    const int ui = tid & 3;
    const int ij = tid >> 2;

    float a0 = 0.f, a1 = 0.f, a2 = 0.f, a3 = 0.f;

    if (ij < HW) {
        const int i = ij / 7;
        const int j = ij - i * 7;
        const int uimax = (i & 1) ? 3 : 4;   // u = (i&1) + 2*ui must be <= 6
        if (ui < uimax) {
            const int u = (i & 1) + 2 * ui;
            const float*  s1p = s1 + ij;
            const float4* s2p = reinterpret_cast<const float4*>(s2f)
                              + ((j & 1) * 7 + u) * S2_STRIDE;

            float dx = 0.f, dy = 0.f, dz = 0.f, dw = 0.f;
            #pragma unroll 4
            for (int c = 0; c < CC; c++) {
                float  a  = s1p[c * 49];     // broadcast across the 4 ui lanes sharing ij
                float4 v4 = s2p[c];          // 4 valid v taps (same parity) at once
                dx = fmaf(a, v4.x, dx);
                dy = fmaf(a, v4.y, dy);
                dz = fmaf(a, v4.z, dz);
                dw = fmaf(a, v4.w, dw);
            }

            // Map back to (p,q) and fold in W for the 4 outputs.
            // p = ui + 10 - (i>>1), q = vi + 10 - (j>>1)
            const int p    = ui + 10 - (i >> 1);
            const int nvi  = (j & 1) ? 3 : 4;
            const int base = p * 1029 + (10 - (j >> 1)) * 49 + ij;
            float d[4] = {dx, dy, dz, dw};
            #pragma unroll
            for (int vi = 0; vi < 4; vi++) {
                if (vi < nvi) {
                    int   fidx = base + vi * 49;
                    float dv   = d[vi];
                    a0 = fmaf(dv, __ldg(W + fidx),            a0);
                    a1 = fmaf(dv, __ldg(W + FEAT     + fidx), a1);
                    a2 = fmaf(dv, __ldg(W + 2 * FEAT + fidx), a2);
                    a3 = fmaf(dv, __ldg(W + 3 * FEAT + fidx), a3);
                }
            }
        }
    }

    // --- Block reduction of the 4 partial outputs ---
    #pragma unroll
    for (int off = 16; off; off >>= 1) {
        a0 += __shfl_down_sync(0xffffffffu, a0, off);
        a1 += __shfl_down_sync(0xffffffffu, a1, off);
        a2 += __shfl_down_sync(0xffffffffu, a2, off);
        a3 += __shfl_down_sync(0xffffffffu, a3, off);
    }
    if ((tid & 31) == 0) {
        int w = tid >> 5;
        wred[w * 4 + 0] = a0;
        wred[w * 4 + 1] = a1;
        wred[w * 4 + 2] = a2;
        wred[w * 4 + 3] = a3;
    }
    __syncthreads();
    if (tid < 4) {
        float s = __ldg(bias + tid);
        #pragma unroll
        for (int w = 0; w < 8; w++) s += wred[w * 4 + tid];
        out[b * 4 + tid] = s;
    }
}

extern "C" void kernel_launch(void* const* d_in, const int* in_sizes, int n_in,
                              void* d_out, int out_size)
{
    (void)in_sizes; (void)n_in; (void)out_size;
    const float* p1 = (const float*)d_in[0];   // patch1 [512,128,7,7]
    const float* p2 = (const float*)d_in[1];   // patch2 [512,128,7,7]
    const float* W  = (const float*)d_in[2];   // w_bbox [4,21609]
    const float* bb = (const float*)d_in[3];   // b_bbox [4]
    float* out = (float*)d_out;                // [512,4] fp32

    // >48KB dynamic smem needs the opt-in attribute. Idempotent; safe under capture
    // (not a stream operation, executes immediately).
    cudaFuncSetAttribute(corr_head_kernel,
                         cudaFuncAttributeMaxDynamicSharedMemorySize, SMEM_BYTES);

    corr_head_kernel<<<512, 256, SMEM_BYTES>>>(p1, p2, W, bb, out);
}

// round 3
// speedup vs baseline: 1.0694x; 1.0694x over previous
#include <cuda_runtime.h>

// CorrelationHead fused, register-tiled.
// out[b,o] = bias[o] + sum over 625 in-bounds (i,j,u,v):
//   W[o, p*1029+q*49+i*7+j] * dot_c( P1[b,c,i,j], P2[b,c,u,v] ),
//   u = i+2(p-10), v = j+2(q-10), both in [0,6]; u≡i, v≡j (mod 2).
//
// Thread layout: tid = slot*8 + cs.  slot = r*4 + ijq, r = (v&1)*7 + u (14 rows),
// ijq picks 4 of the row's (ij) positions. cs splits channels 8-way (c = cs + 8*cl).
// One LDS.128 (4 valid v-taps) feeds 16 FMAs (4 ij x 4 v).

static constexpr int CC        = 128;
static constexpr int FEAT      = 21609;           // 21*21*49
static constexpr int S1_STRIDE = 132;             // [ij][c] pad -> conflict-free a-loads
static constexpr int S1_FLOATS = 49 * S1_STRIDE;  // 6468
static constexpr int S2_STRIDE = 129;             // float4 words per (parity,u) row
static constexpr int S2_F4     = 14 * S2_STRIDE;  // 1806 float4
static constexpr int SMEM_FLOATS = S1_FLOATS + S2_F4 * 4 + 64;
static constexpr int SMEM_BYTES  = SMEM_FLOATS * 4;   // 55,280 B

__global__ __launch_bounds__(448, 3)
void corr_head_kernel(const float* __restrict__ p1,
                      const float* __restrict__ p2,
                      const float* __restrict__ W,
                      const float* __restrict__ bias,
                      float* __restrict__ out)
{
    extern __shared__ float sm[];
    float* s1   = sm;                         // P1 transposed: [ij]*132 + c
    float* s2   = sm + S1_FLOATS;             // P2 rows: float4[(par*7+u)*129 + c], elem = v>>1
    float* wred = sm + S1_FLOATS + S2_F4 * 4; // 14 warps * 4 outputs

    const int b   = blockIdx.x;
    const int tid = threadIdx.x;
    const float* p1b = p1 + (size_t)b * (CC * 49);
    const float* p2b = p2 + (size_t)b * (CC * 49);

    // ---- Stage both inputs: fixed (u,v) per thread, loop c. LDGs coalesced. ----
    {
        int q = tid / 49, uv = tid - q * 49;
        if (q < 9) {
            int u = uv / 7, v = uv - u * 7;
            float* s1dst = s1 + uv * S1_STRIDE;
            float* s2dst = s2 + (((v & 1) * 7 + u) * S2_STRIDE) * 4 + (v >> 1);
            #pragma unroll 1
            for (int c = q; c < CC; c += 9) {
                s1dst[c]     = p1b[c * 49 + uv];
                s2dst[c * 4] = p2b[c * 49 + uv];
            }
        }
    }
    __syncthreads();

    // ---- Per-thread geometry ----
    const int cs   = tid & 7;
    const int slot = tid >> 3;          // 0..55
    const int r    = slot >> 2;         // 0..13
    const int ijq  = slot & 3;
    const int jpar = (r >= 7) ? 1 : 0;
    const int u    = r - jpar * 7;
    const int ipar = u & 1;
    const int ni   = 4 - ipar;          // valid i count (i ≡ u mod 2)
    const int nj   = 4 - jpar;          // valid j count (j ≡ v mod 2)
    const int nvi  = 4 - jpar;          // valid v taps in the float4

    int  ijv[4], wb[4];
    bool vald[4];
    #pragma unroll
    for (int t = 0; t < 4; t++) {
        int  idx = ijq * 4 + t;
        bool v_  = idx < ni * nj;
        int  a_  = (nj == 4) ? (idx >> 2) : (idx / 3);
        int  b_  = idx - a_ * nj;
        int  i_  = ipar + 2 * a_;
        int  j_  = jpar + 2 * b_;
        int  ij  = i_ * 7 + j_;
        vald[t] = v_;
        ijv[t]  = v_ ? ij : 0;
        // p = 10 + (u-i)/2 = 10 + (u>>1) - a ;  q(vi) = 10 - b + vi
        wb[t]   = (10 + (u >> 1) - a_) * 1029 + (10 - b_) * 49 + ij;
    }

    const float* a0p = s1 + ijv[0] * S1_STRIDE + cs;
    const float* a1p = s1 + ijv[1] * S1_STRIDE + cs;
    const float* a2p = s1 + ijv[2] * S1_STRIDE + cs;
    const float* a3p = s1 + ijv[3] * S1_STRIDE + cs;
    const float4* vp = reinterpret_cast<const float4*>(s2) + r * S2_STRIDE + cs;

    float4 dot0 = {0,0,0,0}, dot1 = {0,0,0,0}, dot2 = {0,0,0,0}, dot3 = {0,0,0,0};

    // ---- Main loop: 16 c-steps (c = cs + 8*cl), fully unrolled immediate offsets ----
    #pragma unroll
    for (int cl = 0; cl < 16; cl++) {
        float4 v4 = vp[cl * 8];
        float x0 = a0p[cl * 8];
        float x1 = a1p[cl * 8];
        float x2 = a2p[cl * 8];
        float x3 = a3p[cl * 8];
        dot0.x = fmaf(x0, v4.x, dot0.x); dot0.y = fmaf(x0, v4.y, dot0.y);
        dot0.z = fmaf(x0, v4.z, dot0.z); dot0.w = fmaf(x0, v4.w, dot0.w);
        dot1.x = fmaf(x1, v4.x, dot1.x); dot1.y = fmaf(x1, v4.y, dot1.y);
        dot1.z = fmaf(x1, v4.z, dot1.z); dot1.w = fmaf(x1, v4.w, dot1.w);
        dot2.x = fmaf(x2, v4.x, dot2.x); dot2.y = fmaf(x2, v4.y, dot2.y);
        dot2.z = fmaf(x2, v4.z, dot2.z); dot2.w = fmaf(x2, v4.w, dot2.w);
        dot3.x = fmaf(x3, v4.x, dot3.x); dot3.y = fmaf(x3, v4.y, dot3.y);
        dot3.z = fmaf(x3, v4.z, dot3.z); dot3.w = fmaf(x3, v4.w, dot3.w);
    }

    // ---- Reduce partial dots across the 8 cs lanes (adjacent lanes) ----
    const unsigned FULL = 0xffffffffu;
    #pragma unroll
    for (int off = 1; off < 8; off <<= 1) {
        dot0.x += __shfl_xor_sync(FULL, dot0.x, off);
        dot0.y += __shfl_xor_sync(FULL, dot0.y, off);
        dot0.z += __shfl_xor_sync(FULL, dot0.z, off);
        dot0.w += __shfl_xor_sync(FULL, dot0.w, off);
        dot1.x += __shfl_xor_sync(FULL, dot1.x, off);
        dot1.y += __shfl_xor_sync(FULL, dot1.y, off);
        dot1.z += __shfl_xor_sync(FULL, dot1.z, off);
        dot1.w += __shfl_xor_sync(FULL, dot1.w, off);
        dot2.x += __shfl_xor_sync(FULL, dot2.x, off);
        dot2.y += __shfl_xor_sync(FULL, dot2.y, off);
        dot2.z += __shfl_xor_sync(FULL, dot2.z, off);
        dot2.w += __shfl_xor_sync(FULL, dot2.w, off);
        dot3.x += __shfl_xor_sync(FULL, dot3.x, off);
        dot3.y += __shfl_xor_sync(FULL, dot3.y, off);
        dot3.z += __shfl_xor_sync(FULL, dot3.z, off);
        dot3.w += __shfl_xor_sync(FULL, dot3.w, off);
    }

    // ---- W gather spread over all lanes: cs = o + 4*h, h picks vi-pair ----
    const int o = cs & 3;
    const int h = cs >> 2;
    const float* Wo = W + o * FEAT;
    float part = 0.f;
    {
        const float4 dts[4] = {dot0, dot1, dot2, dot3};
        #pragma unroll
        for (int k = 0; k < 4; k++) {
            if (vald[k]) {
                float dlo = h ? dts[k].z : dts[k].x;   // vi = 2h
                float dhi = h ? dts[k].w : dts[k].y;   // vi = 2h+1
                int   f0  = wb[k] + (2 * h) * 49;
                part = fmaf(dlo, __ldg(Wo + f0), part);
                if (2 * h + 1 < nvi)                    // only excludes h=1, jpar=1
                    part = fmaf(dhi, __ldg(Wo + f0 + 49), part);
            }
        }
    }

    // ---- Combine: lanes (cs,cs+4) same o, then 4 slots per warp ----
    part += __shfl_down_sync(FULL, part, 4);
    part += __shfl_down_sync(FULL, part, 8);
    part += __shfl_down_sync(FULL, part, 16);
    const int lane = tid & 31;
    if (lane < 4) wred[(tid >> 5) * 4 + lane] = part;   // lane == o here
    __syncthreads();

    if (tid < 4) {
        float s = __ldg(bias + tid);
        #pragma unroll
        for (int w = 0; w < 14; w++) s += wred[w * 4 + tid];
        out[b * 4 + tid] = s;
    }
}

extern "C" void kernel_launch(void* const* d_in, const int* in_sizes, int n_in,
                              void* d_out, int out_size)
{
    (void)in_sizes; (void)n_in; (void)out_size;
    const float* p1 = (const float*)d_in[0];   // patch1 [512,128,7,7]
    const float* p2 = (const float*)d_in[1];   // patch2 [512,128,7,7]
    const float* W  = (const float*)d_in[2];   // w_bbox [4,21609]
    const float* bb = (const float*)d_in[3];   // b_bbox [4]
    float* out = (float*)d_out;                // [512,4] fp32

    cudaFuncSetAttribute(corr_head_kernel,
                         cudaFuncAttributeMaxDynamicSharedMemorySize, SMEM_BYTES);

    corr_head_kernel<<<512, 448, SMEM_BYTES>>>(p1, p2, W, bb, out);
}

// round 7
// speedup vs baseline: 1.0891x; 1.0184x over previous
#include <cuda_runtime.h>

// CorrelationHead fused, register-tiled, single-wave (occ 4).
// out[b,o] = bias[o] + sum over 625 in-bounds (i,j,u,v):
//   W[o, p*1029+q*49+i*7+j] * dot_c( P1[b,c,i,j], P2[b,c,u,v] ),
//   u = i+2(p-10), v = j+2(q-10), both in [0,6]; u≡i (mod 2), v≡j (mod 2).
//
// tid = slot*8 + cs.  slot = r*4 + ijq, r = (v&1)*7 + u (14 rows).
// One LDS.128 (4 valid v-taps, same parity) feeds 16 FMAs (4 ij x 4 v).
// c split 8 ways across cs; partials reduced via shfl.

static constexpr int CC        = 128;
static constexpr int FEAT      = 21609;           // 21*21*49
static constexpr int S1_STRIDE = 132;             // [ij][c] pad -> conflict-free a-loads
static constexpr int S1_FLOATS = 49 * S1_STRIDE;  // 6468
static constexpr int S2_STRIDE = 129;             // float4 words per (parity,u) row
static constexpr int S2_F4     = 14 * S2_STRIDE;  // 1806 float4
static constexpr int SMEM_FLOATS = S1_FLOATS + S2_F4 * 4 + 64;
static constexpr int SMEM_BYTES  = SMEM_FLOATS * 4;   // 55,280 B  (4/SM = 221 KB <= 228 KB)

__global__ __launch_bounds__(448, 4)
void corr_head_kernel(const float* __restrict__ p1,
                      const float* __restrict__ p2,
                      const float* __restrict__ W,
                      const float* __restrict__ bias,
                      float* __restrict__ out)
{
    extern __shared__ float sm[];
    float* s1   = sm;                         // P1 transposed: [ij]*132 + c
    float* s2   = sm + S1_FLOATS;             // P2 rows: float4[(par*7+u)*129 + c], elem = v>>1
    float* wred = sm + S1_FLOATS + S2_F4 * 4; // 14 warps * 4 outputs

    const int b   = blockIdx.x;
    const int tid = threadIdx.x;
    const float* p1b = p1 + (size_t)b * (CC * 49);
    const float* p2b = p2 + (size_t)b * (CC * 49);

    // ---- Stage both inputs: fixed (u,v) per thread, loop c. LDGs coalesced. ----
    {
        int q = tid / 49, uv = tid - q * 49;
        if (q < 9) {
            int u = uv / 7, v = uv - u * 7;
            int s1off = uv * S1_STRIDE;
            int s2off = (((v & 1) * 7 + u) * S2_STRIDE) * 4 + (v >> 1);
            #pragma unroll 1
            for (int c = q; c < CC; c += 9) {
                s1[s1off + c]     = p1b[c * 49 + uv];
                s2[s2off + c * 4] = p2b[c * 49 + uv];
            }
        }
    }
    __syncthreads();

    // ---- Per-thread geometry (loop-live part only) ----
    const int cs   = tid & 7;
    const int slot = tid >> 3;          // 0..55
    const int r    = slot >> 2;         // 0..13
    const int ijq  = slot & 3;
    const int jpar = (r >= 7) ? 1 : 0;
    const int u    = r - jpar * 7;
    const int ipar = u & 1;
    const int ni   = 4 - ipar;          // valid i count
    const int nj   = 4 - jpar;          // valid j count

    int ijoff[4];
    #pragma unroll
    for (int t = 0; t < 4; t++) {
        int idx = ijq * 4 + t;
        int a_  = (nj == 4) ? (idx >> 2) : (idx / 3);
        int b_  = idx - a_ * nj;
        int ij  = (ipar + 2 * a_) * 7 + (jpar + 2 * b_);
        ijoff[t] = ((idx < ni * nj) ? ij : 0) * S1_STRIDE + cs;
    }

    const int vbase = (r * S2_STRIDE + cs) * 4;   // float index into s2

    float4 dot0 = {0,0,0,0}, dot1 = {0,0,0,0}, dot2 = {0,0,0,0}, dot3 = {0,0,0,0};

    // ---- Main loop: 16 c-steps (c = cs + 8*cl), fully unrolled immediate offsets ----
    #pragma unroll
    for (int cl = 0; cl < 16; cl++) {
        float4 v4 = *reinterpret_cast<const float4*>(s2 + vbase + cl * 32);
        float x0 = s1[ijoff[0] + cl * 8];
        float x1 = s1[ijoff[1] + cl * 8];
        float x2 = s1[ijoff[2] + cl * 8];
        float x3 = s1[ijoff[3] + cl * 8];
        dot0.x = fmaf(x0, v4.x, dot0.x); dot0.y = fmaf(x0, v4.y, dot0.y);
        dot0.z = fmaf(x0, v4.z, dot0.z); dot0.w = fmaf(x0, v4.w, dot0.w);
        dot1.x = fmaf(x1, v4.x, dot1.x); dot1.y = fmaf(x1, v4.y, dot1.y);
        dot1.z = fmaf(x1, v4.z, dot1.z); dot1.w = fmaf(x1, v4.w, dot1.w);
        dot2.x = fmaf(x2, v4.x, dot2.x); dot2.y = fmaf(x2, v4.y, dot2.y);
        dot2.z = fmaf(x2, v4.z, dot2.z); dot2.w = fmaf(x2, v4.w, dot2.w);
        dot3.x = fmaf(x3, v4.x, dot3.x); dot3.y = fmaf(x3, v4.y, dot3.y);
        dot3.z = fmaf(x3, v4.z, dot3.z); dot3.w = fmaf(x3, v4.w, dot3.w);
    }

    // ---- Reduce partial dots across the 8 cs lanes ----
    const unsigned FULL = 0xffffffffu;
    #pragma unroll
    for (int off = 1; off < 8; off <<= 1) {
        dot0.x += __shfl_xor_sync(FULL, dot0.x, off);
        dot0.y += __shfl_xor_sync(FULL, dot0.y, off);
        dot0.z += __shfl_xor_sync(FULL, dot0.z, off);
        dot0.w += __shfl_xor_sync(FULL, dot0.w, off);
        dot1.x += __shfl_xor_sync(FULL, dot1.x, off);
        dot1.y += __shfl_xor_sync(FULL, dot1.y, off);
        dot1.z += __shfl_xor_sync(FULL, dot1.z, off);
        dot1.w += __shfl_xor_sync(FULL, dot1.w, off);
        dot2.x += __shfl_xor_sync(FULL, dot2.x, off);
        dot2.y += __shfl_xor_sync(FULL, dot2.y, off);
        dot2.z += __shfl_xor_sync(FULL, dot2.z, off);
        dot2.w += __shfl_xor_sync(FULL, dot2.w, off);
        dot3.x += __shfl_xor_sync(FULL, dot3.x, off);
        dot3.y += __shfl_xor_sync(FULL, dot3.y, off);
        dot3.z += __shfl_xor_sync(FULL, dot3.z, off);
        dot3.w += __shfl_xor_sync(FULL, dot3.w, off);
    }

    // ---- W gather spread over all lanes: cs = o + 4*h, h picks the vi-pair ----
    // Geometry (wb / validity) recomputed HERE so it is not live across the loop.
    const int o = cs & 3;
    const int h = cs >> 2;
    const int nvi = 4 - jpar;
    const float* Wo = W + o * FEAT;
    float part = 0.f;
    {
        const float4 dts[4] = {dot0, dot1, dot2, dot3};
        #pragma unroll
        for (int t = 0; t < 4; t++) {
            int idx = ijq * 4 + t;
            if (idx < ni * nj) {
                int a_  = (nj == 4) ? (idx >> 2) : (idx / 3);
                int b_  = idx - a_ * nj;
                int ij  = (ipar + 2 * a_) * 7 + (jpar + 2 * b_);
                int wb  = (10 + (u >> 1) - a_) * 1029 + (10 - b_) * 49 + ij;
                float dlo = h ? dts[t].z : dts[t].x;   // vi = 2h
                float dhi = h ? dts[t].w : dts[t].y;   // vi = 2h+1
                int   f0  = wb + (2 * h) * 49;
                part = fmaf(dlo, __ldg(Wo + f0), part);
                if (2 * h + 1 < nvi)                    // excludes only h=1, jpar=1
                    part = fmaf(dhi, __ldg(Wo + f0 + 49), part);
            }
        }
    }

    // ---- Combine: lanes (cs,cs+4) same o, then 4 slots per warp, then 14 warps ----
    part += __shfl_down_sync(FULL, part, 4);
    part += __shfl_down_sync(FULL, part, 8);
    part += __shfl_down_sync(FULL, part, 16);
    const int lane = tid & 31;
    if (lane < 4) wred[(tid >> 5) * 4 + lane] = part;   // lane == o here
    __syncthreads();

    if (tid < 4) {
        float s = __ldg(bias + tid);
        #pragma unroll
        for (int w = 0; w < 14; w++) s += wred[w * 4 + tid];
        out[b * 4 + tid] = s;
    }
}

extern "C" void kernel_launch(void* const* d_in, const int* in_sizes, int n_in,
                              void* d_out, int out_size)
{
    (void)in_sizes; (void)n_in; (void)out_size;
    const float* p1 = (const float*)d_in[0];   // patch1 [512,128,7,7]
    const float* p2 = (const float*)d_in[1];   // patch2 [512,128,7,7]
    const float* W  = (const float*)d_in[2];   // w_bbox [4,21609]
    const float* bb = (const float*)d_in[3];   // b_bbox [4]
    float* out = (float*)d_out;                // [512,4] fp32

    cudaFuncSetAttribute(corr_head_kernel,
                         cudaFuncAttributeMaxDynamicSharedMemorySize, SMEM_BYTES);

    corr_head_kernel<<<512, 448, SMEM_BYTES>>>(p1, p2, W, bb, out);
}

// round 10
// speedup vs baseline: 1.1756x; 1.0794x over previous
#include <cuda_runtime.h>

// CorrelationHead fused, register-tiled, single-wave, high-ILP variant.
// out[b,o] = bias[o] + sum over 625 in-bounds (i,j,u,v):
//   W[o, p*1029+q*49+i*7+j] * dot_c( P1[b,c,i,j], P2[b,c,u,v] ),
//   u = i+2(p-10), v = j+2(q-10), both in [0,6]; u≡i (mod 2), v≡j (mod 2).
//
// tid = slot*4 + cs (cs in 0..3).  slot = r*4 + ijq, r = (v&1)*7 + u (14 rows).
// c = cs + 4*cl, cl = 0..31.  One LDS.128 (4 v-taps) feeds 16 FMAs (4 ij x 4 v).
// 224 threads/block -> 72-reg budget at occ 4 -> ptxas can pipeline smem loads.

static constexpr int CC        = 128;
static constexpr int FEAT      = 21609;           // 21*21*49
static constexpr int S1_STRIDE = 132;             // floats per ij row (conflict-free a-loads)
static constexpr int S1_FLOATS = 49 * S1_STRIDE;  // 6468
static constexpr int S2_ROWF4  = 132;             // float4 per (parity,u) row; 132%8==4 -> v4 tiles banks
static constexpr int S2_ROW    = S2_ROWF4 * 4;    // 528 floats
static constexpr int S2_FLOATS = 14 * S2_ROW;     // 7392
static constexpr int SMEM_FLOATS = S1_FLOATS + S2_FLOATS + 32;
static constexpr int SMEM_BYTES  = SMEM_FLOATS * 4;   // 55,568 B (4/SM = 222 KB <= 228 KB)

__global__ __launch_bounds__(224, 4)
void corr_head_kernel(const float* __restrict__ p1,
                      const float* __restrict__ p2,
                      const float* __restrict__ W,
                      const float* __restrict__ bias,
                      float* __restrict__ out)
{
    extern __shared__ float sm[];
    float* s1   = sm;                         // P1: [ij]*132 + c
    float* s2   = sm + S1_FLOATS;             // P2: row r' = (v&1)*7+u, float4[c], elem v>>1
    float* wred = sm + S1_FLOATS + S2_FLOATS; // 7 warps * 4 outputs

    const int b   = blockIdx.x;
    const int tid = threadIdx.x;
    const float* p1b = p1 + (size_t)b * (CC * 49);
    const float* p2b = p2 + (size_t)b * (CC * 49);

    // ---- Stage both inputs. 196 threads: cq = tid/49, uv = tid%49, c = cq+4*cl. ----
    if (tid < 196) {
        const int cq = tid / 49;
        const int uv = tid - cq * 49;
        const int u  = uv / 7;
        const int v  = uv - u * 7;
        const int s1off = uv * S1_STRIDE + cq;                       // + 4*cl
        const int s2off = ((v & 1) * 7 + u) * S2_ROW + (v >> 1) + cq * 4;  // + 16*cl
        const int goff  = cq * 49 + uv;                              // + 196*cl
        #pragma unroll 8
        for (int cl = 0; cl < 32; cl++) {
            s1[s1off + cl * 4]  = p1b[goff + cl * 196];
            s2[s2off + cl * 16] = p2b[goff + cl * 196];
        }
    }
    __syncthreads();

    // ---- Per-thread geometry ----
    const int cs   = tid & 3;
    const int slot = tid >> 2;          // 0..55
    const int r    = slot >> 2;         // 0..13
    const int ijq  = slot & 3;
    const int jpar = (r >= 7) ? 1 : 0;
    const int u    = r - jpar * 7;
    const int ipar = u & 1;
    const int ni   = 4 - ipar;
    const int nj   = 4 - jpar;

    int ijoff[4];
    #pragma unroll
    for (int t = 0; t < 4; t++) {
        int idx = ijq * 4 + t;
        int a_  = (nj == 4) ? (idx >> 2) : (idx / 3);
        int b_  = idx - a_ * nj;
        int ij  = (ipar + 2 * a_) * 7 + (jpar + 2 * b_);
        ijoff[t] = ((idx < ni * nj) ? ij : 0) * S1_STRIDE + cs;
    }
    const int vbase = r * S2_ROW + cs * 4;   // float index of this thread's float4

    float4 dot0 = {0,0,0,0}, dot1 = {0,0,0,0}, dot2 = {0,0,0,0}, dot3 = {0,0,0,0};

    // ---- Main loop: 32 c-steps, fully unrolled; regs allow multi-step prefetch ----
    #pragma unroll
    for (int cl = 0; cl < 32; cl++) {
        float4 v4 = *reinterpret_cast<const float4*>(s2 + vbase + cl * 16);
        float x0 = s1[ijoff[0] + cl * 4];
        float x1 = s1[ijoff[1] + cl * 4];
        float x2 = s1[ijoff[2] + cl * 4];
        float x3 = s1[ijoff[3] + cl * 4];
        dot0.x = fmaf(x0, v4.x, dot0.x); dot0.y = fmaf(x0, v4.y, dot0.y);
        dot0.z = fmaf(x0, v4.z, dot0.z); dot0.w = fmaf(x0, v4.w, dot0.w);
        dot1.x = fmaf(x1, v4.x, dot1.x); dot1.y = fmaf(x1, v4.y, dot1.y);
        dot1.z = fmaf(x1, v4.z, dot1.z); dot1.w = fmaf(x1, v4.w, dot1.w);
        dot2.x = fmaf(x2, v4.x, dot2.x); dot2.y = fmaf(x2, v4.y, dot2.y);
        dot2.z = fmaf(x2, v4.z, dot2.z); dot2.w = fmaf(x2, v4.w, dot2.w);
        dot3.x = fmaf(x3, v4.x, dot3.x); dot3.y = fmaf(x3, v4.y, dot3.y);
        dot3.z = fmaf(x3, v4.z, dot3.z); dot3.w = fmaf(x3, v4.w, dot3.w);
    }

    // ---- Reduce partials across the 4 cs lanes (2 shfl levels) ----
    const unsigned FULL = 0xffffffffu;
    #pragma unroll
    for (int off = 1; off < 4; off <<= 1) {
        dot0.x += __shfl_xor_sync(FULL, dot0.x, off);
        dot0.y += __shfl_xor_sync(FULL, dot0.y, off);
        dot0.z += __shfl_xor_sync(FULL, dot0.z, off);
        dot0.w += __shfl_xor_sync(FULL, dot0.w, off);
        dot1.x += __shfl_xor_sync(FULL, dot1.x, off);
        dot1.y += __shfl_xor_sync(FULL, dot1.y, off);
        dot1.z += __shfl_xor_sync(FULL, dot1.z, off);
        dot1.w += __shfl_xor_sync(FULL, dot1.w, off);
        dot2.x += __shfl_xor_sync(FULL, dot2.x, off);
        dot2.y += __shfl_xor_sync(FULL, dot2.y, off);
        dot2.z += __shfl_xor_sync(FULL, dot2.z, off);
        dot2.w += __shfl_xor_sync(FULL, dot2.w, off);
        dot3.x += __shfl_xor_sync(FULL, dot3.x, off);
        dot3.y += __shfl_xor_sync(FULL, dot3.y, off);
        dot3.z += __shfl_xor_sync(FULL, dot3.z, off);
        dot3.w += __shfl_xor_sync(FULL, dot3.w, off);
    }

    // ---- W gather: each cs lane handles output o = cs; <=16 independent L2 loads ----
    const float* Wo = W + cs * FEAT;
    float part = 0.f;
    {
        const float4 dts[4] = {dot0, dot1, dot2, dot3};
        const int nvi = 4 - jpar;
        #pragma unroll
        for (int t = 0; t < 4; t++) {
            int idx = ijq * 4 + t;
            if (idx < ni * nj) {
                int a_  = (nj == 4) ? (idx >> 2) : (idx / 3);
                int b_  = idx - a_ * nj;
                int ij  = (ipar + 2 * a_) * 7 + (jpar + 2 * b_);
                int wb  = (10 + (u >> 1) - a_) * 1029 + (10 - b_) * 49 + ij;
                part = fmaf(dts[t].x, __ldg(Wo + wb),           part);
                part = fmaf(dts[t].y, __ldg(Wo + wb + 49),      part);
                part = fmaf(dts[t].z, __ldg(Wo + wb + 98),      part);
                if (nvi == 4)
                    part = fmaf(dts[t].w, __ldg(Wo + wb + 147), part);
            }
        }
    }

    // ---- Combine: 8 slots per warp via shfl, then 7 warps via smem ----
    part += __shfl_down_sync(FULL, part, 4);
    part += __shfl_down_sync(FULL, part, 8);
    part += __shfl_down_sync(FULL, part, 16);
    const int lane = tid & 31;
    if (lane < 4) wred[(tid >> 5) * 4 + lane] = part;   // lane == cs == o here
    __syncthreads();

    if (tid < 4) {
        float s = __ldg(bias + tid);
        #pragma unroll
        for (int w = 0; w < 7; w++) s += wred[w * 4 + tid];
        out[b * 4 + tid] = s;
    }
}

extern "C" void kernel_launch(void* const* d_in, const int* in_sizes, int n_in,
                              void* d_out, int out_size)
{
    (void)in_sizes; (void)n_in; (void)out_size;
    const float* p1 = (const float*)d_in[0];   // patch1 [512,128,7,7]
    const float* p2 = (const float*)d_in[1];   // patch2 [512,128,7,7]
    const float* W  = (const float*)d_in[2];   // w_bbox [4,21609]
    const float* bb = (const float*)d_in[3];   // b_bbox [4]
    float* out = (float*)d_out;                // [512,4] fp32

    cudaFuncSetAttribute(corr_head_kernel,
                         cudaFuncAttributeMaxDynamicSharedMemorySize, SMEM_BYTES);

    corr_head_kernel<<<512, 224, SMEM_BYTES>>>(p1, p2, W, bb, out);
}

// round 11
// speedup vs baseline: 1.5010x; 1.2768x over previous
#include <cuda_runtime.h>
#include <cstdint>

// CorrelationHead fused. Raw-layout smem staged via cp.async.bulk (UBLKCP),
// 2-stage c-split pipeline, W prefetched to registers.
// out[b,o] = bias[o] + sum over 625 in-bounds (i,j,u,v):
//   W[o, p*1029+q*49+i*7+j] * dot_c( P1[b,c,i,j], P2[b,c,u,v] ),
//   u = i+2(p-10), v = j+2(q-10) in [0,6]; u≡i (mod 2), v≡j (mod 2).
//
// tid = slot*4 + cs. slot = r*4 + ijq, r = (v&1)*7 + u (14 rows). c = cs + 4*cl.
// Per iter: 4 x-taps (ij) x 4 y-taps (v) -> 16 FMAs from 8 LDS.32.

static constexpr int FEAT   = 21609;        // 21*21*49
static constexpr int TEN    = 6272;         // 128*49 floats per tensor per batch
static constexpr int HALF_B = (TEN / 2) * 4;  // 12544 bytes per c-half
static constexpr int S2_OFF   = TEN;
static constexpr int WRED_OFF = 2 * TEN + 16;          // 16-float pad absorbs y OOB tap
static constexpr int MBAR_B   = (WRED_OFF + 32) * 4;   // byte offset of mbarriers (8-aligned)
static constexpr int SMEM_BYTES = MBAR_B + 16;         // two 8B mbarriers

__global__ __launch_bounds__(224, 4)
void corr_head_kernel(const float* __restrict__ p1,
                      const float* __restrict__ p2,
                      const float* __restrict__ W,
                      const float* __restrict__ bias,
                      float* __restrict__ out)
{
    extern __shared__ float sm[];
    float* s1   = sm;             // P1 raw: [c*49 + uv]
    float* s2   = sm + S2_OFF;    // P2 raw: [c*49 + uv]
    float* wred = sm + WRED_OFF;  // 7 warps * 4 outputs

    uint32_t smem_u32;
    asm("{ .reg .u64 t; cvta.to.shared.u64 t, %1; cvt.u32.u64 %0, t; }"
        : "=r"(smem_u32) : "l"(sm));
    const uint32_t mbar0 = smem_u32 + MBAR_B;
    const uint32_t mbar1 = mbar0 + 8;

    const int b   = blockIdx.x;
    const int tid = threadIdx.x;
    const float* p1b = p1 + (size_t)b * TEN;
    const float* p2b = p2 + (size_t)b * TEN;

    // ---- Async staging: 4 bulk copies, two completion barriers (c-halves) ----
    if (tid == 0) {
        asm volatile("mbarrier.init.shared.b64 [%0], 1;" :: "r"(mbar0) : "memory");
        asm volatile("mbarrier.init.shared.b64 [%0], 1;" :: "r"(mbar1) : "memory");
    }
    __syncthreads();
    if (tid == 0) {
        const uint32_t d1 = smem_u32;
        const uint32_t d2 = smem_u32 + TEN * 4;
        asm volatile("mbarrier.arrive.expect_tx.shared.b64 _, [%0], %1;"
                     :: "r"(mbar0), "r"(2 * HALF_B) : "memory");
        asm volatile("cp.async.bulk.shared::cluster.global.mbarrier::complete_tx::bytes [%0], [%1], %2, [%3];"
                     :: "r"(d1), "l"(p1b), "r"(HALF_B), "r"(mbar0) : "memory");
        asm volatile("cp.async.bulk.shared::cluster.global.mbarrier::complete_tx::bytes [%0], [%1], %2, [%3];"
                     :: "r"(d2), "l"(p2b), "r"(HALF_B), "r"(mbar0) : "memory");
        asm volatile("mbarrier.arrive.expect_tx.shared.b64 _, [%0], %1;"
                     :: "r"(mbar1), "r"(2 * HALF_B) : "memory");
        asm volatile("cp.async.bulk.shared::cluster.global.mbarrier::complete_tx::bytes [%0], [%1], %2, [%3];"
                     :: "r"(d1 + HALF_B), "l"(p1b + TEN / 2), "r"(HALF_B), "r"(mbar1) : "memory");
        asm volatile("cp.async.bulk.shared::cluster.global.mbarrier::complete_tx::bytes [%0], [%1], %2, [%3];"
                     :: "r"(d2 + HALF_B), "l"(p2b + TEN / 2), "r"(HALF_B), "r"(mbar1) : "memory");
    }

    // ---- Per-thread geometry ----
    const int cs   = tid & 3;
    const int slot = tid >> 2;          // 0..55
    const int r    = slot >> 2;         // 0..13
    const int ijq  = slot & 3;
    const int jpar = (r >= 7) ? 1 : 0;
    const int u    = r - jpar * 7;
    const int ipar = u & 1;
    const int ni   = 4 - ipar;
    const int nj   = 4 - jpar;
    const int nvi  = 4 - jpar;

    int xb[4];
    #pragma unroll
    for (int t = 0; t < 4; t++) {
        int idx = ijq * 4 + t;
        int a_  = (nj == 4) ? (idx >> 2) : (idx / 3);
        int b_  = idx - a_ * nj;
        int ij  = (ipar + 2 * a_) * 7 + (jpar + 2 * b_);
        xb[t]   = ((idx < ni * nj) ? ij : 0) + cs * 49;
    }
    const int yb = u * 7 + jpar + cs * 49;

    // ---- Prefetch W into registers (overlaps with bulk copies in flight) ----
    float wv[16];
    {
        const float* Wo = W + cs * FEAT;
        #pragma unroll
        for (int t = 0; t < 4; t++) {
            int idx = ijq * 4 + t;
            bool val = idx < ni * nj;
            int a_  = (nj == 4) ? (idx >> 2) : (idx / 3);
            int b_  = idx - a_ * nj;
            int ij  = (ipar + 2 * a_) * 7 + (jpar + 2 * b_);
            int wb  = (10 + (u >> 1) - a_) * 1029 + (10 - b_) * 49 + ij;
            wv[t*4+0] = val ? __ldg(Wo + wb)       : 0.f;
            wv[t*4+1] = val ? __ldg(Wo + wb + 49)  : 0.f;
            wv[t*4+2] = val ? __ldg(Wo + wb + 98)  : 0.f;
            wv[t*4+3] = (val && nvi == 4) ? __ldg(Wo + wb + 147) : 0.f;
        }
    }

    float4 dot0 = {0,0,0,0}, dot1 = {0,0,0,0}, dot2 = {0,0,0,0}, dot3 = {0,0,0,0};

    #define MBAR_WAIT(mb) do {                                                    \
        asm volatile("{\n\t.reg .pred P;\n\t"                                     \
                     "WL_%=:\n\t"                                                 \
                     "mbarrier.try_wait.parity.acquire.cta.shared::cta.b64 P, [%0], 0, 0x989680;\n\t" \
                     "@!P bra WL_%=;\n\t}"                                        \
                     :: "r"(mb) : "memory");                                      \
    } while (0)

    #define BODY(cl) do {                                                         \
        const int off = (cl) * 196;                                               \
        float y0 = s2[yb + off];                                                  \
        float y1 = s2[yb + off + 2];                                              \
        float y2 = s2[yb + off + 4];                                              \
        float y3 = s2[yb + off + 6];                                              \
        float x0 = s1[xb[0] + off];                                               \
        float x1 = s1[xb[1] + off];                                               \
        float x2 = s1[xb[2] + off];                                               \
        float x3 = s1[xb[3] + off];                                               \
        dot0.x = fmaf(x0, y0, dot0.x); dot0.y = fmaf(x0, y1, dot0.y);             \
        dot0.z = fmaf(x0, y2, dot0.z); dot0.w = fmaf(x0, y3, dot0.w);             \
        dot1.x = fmaf(x1, y0, dot1.x); dot1.y = fmaf(x1, y1, dot1.y);             \
        dot1.z = fmaf(x1, y2, dot1.z); dot1.w = fmaf(x1, y3, dot1.w);             \
        dot2.x = fmaf(x2, y0, dot2.x); dot2.y = fmaf(x2, y1, dot2.y);             \
        dot2.z = fmaf(x2, y2, dot2.z); dot2.w = fmaf(x2, y3, dot2.w);             \
        dot3.x = fmaf(x3, y0, dot3.x); dot3.y = fmaf(x3, y1, dot3.y);             \
        dot3.z = fmaf(x3, y2, dot3.z); dot3.w = fmaf(x3, y3, dot3.w);             \
    } while (0)

    // ---- Half 1: c = 0..63 (cl 0..15) ----
    MBAR_WAIT(mbar0);
    #pragma unroll
    for (int cl = 0; cl < 16; cl++) BODY(cl);

    // ---- Half 2: c = 64..127 (cl 16..31) ----
    MBAR_WAIT(mbar1);
    #pragma unroll
    for (int cl = 16; cl < 32; cl++) BODY(cl);

    #undef BODY
    #undef MBAR_WAIT

    // ---- Reduce partial dots across the 4 cs lanes ----
    const unsigned FULL = 0xffffffffu;
    #pragma unroll
    for (int off = 1; off < 4; off <<= 1) {
        dot0.x += __shfl_xor_sync(FULL, dot0.x, off);
        dot0.y += __shfl_xor_sync(FULL, dot0.y, off);
        dot0.z += __shfl_xor_sync(FULL, dot0.z, off);
        dot0.w += __shfl_xor_sync(FULL, dot0.w, off);
        dot1.x += __shfl_xor_sync(FULL, dot1.x, off);
        dot1.y += __shfl_xor_sync(FULL, dot1.y, off);
        dot1.z += __shfl_xor_sync(FULL, dot1.z, off);
        dot1.w += __shfl_xor_sync(FULL, dot1.w, off);
        dot2.x += __shfl_xor_sync(FULL, dot2.x, off);
        dot2.y += __shfl_xor_sync(FULL, dot2.y, off);
        dot2.z += __shfl_xor_sync(FULL, dot2.z, off);
        dot2.w += __shfl_xor_sync(FULL, dot2.w, off);
        dot3.x += __shfl_xor_sync(FULL, dot3.x, off);
        dot3.y += __shfl_xor_sync(FULL, dot3.y, off);
        dot3.z += __shfl_xor_sync(FULL, dot3.z, off);
        dot3.w += __shfl_xor_sync(FULL, dot3.w, off);
    }

    // ---- Epilogue: branchless W combine (invalid/unused taps have wv = 0) ----
    float part = 0.f;
    part = fmaf(dot0.x, wv[0],  part); part = fmaf(dot0.y, wv[1],  part);
    part = fmaf(dot0.z, wv[2],  part); part = fmaf(dot0.w, wv[3],  part);
    part = fmaf(dot1.x, wv[4],  part); part = fmaf(dot1.y, wv[5],  part);
    part = fmaf(dot1.z, wv[6],  part); part = fmaf(dot1.w, wv[7],  part);
    part = fmaf(dot2.x, wv[8],  part); part = fmaf(dot2.y, wv[9],  part);
    part = fmaf(dot2.z, wv[10], part); part = fmaf(dot2.w, wv[11], part);
    part = fmaf(dot3.x, wv[12], part); part = fmaf(dot3.y, wv[13], part);
    part = fmaf(dot3.z, wv[14], part); part = fmaf(dot3.w, wv[15], part);

    // ---- Combine: 8 slots per warp via shfl, then 7 warps via smem ----
    part += __shfl_down_sync(FULL, part, 4);
    part += __shfl_down_sync(FULL, part, 8);
    part += __shfl_down_sync(FULL, part, 16);
    const int lane = tid & 31;
    if (lane < 4) wred[(tid >> 5) * 4 + lane] = part;   // lane == cs == o here
    __syncthreads();

    if (tid < 4) {
        float s = __ldg(bias + tid);
        #pragma unroll
        for (int w = 0; w < 7; w++) s += wred[w * 4 + tid];
        out[b * 4 + tid] = s;
    }
}

extern "C" void kernel_launch(void* const* d_in, const int* in_sizes, int n_in,
                              void* d_out, int out_size)
{
    (void)in_sizes; (void)n_in; (void)out_size;
    const float* p1 = (const float*)d_in[0];   // patch1 [512,128,7,7]
    const float* p2 = (const float*)d_in[1];   // patch2 [512,128,7,7]
    const float* W  = (const float*)d_in[2];   // w_bbox [4,21609]
    const float* bb = (const float*)d_in[3];   // b_bbox [4]
    float* out = (float*)d_out;                // [512,4] fp32

    cudaFuncSetAttribute(corr_head_kernel,
                         cudaFuncAttributeMaxDynamicSharedMemorySize, SMEM_BYTES);

    corr_head_kernel<<<512, 224, SMEM_BYTES>>>(p1, p2, W, bb, out);
}